// round 5
// baseline (speedup 1.0000x reference)
#include <cuda_runtime.h>
#include <cstdint>

// Problem dims
#define DM 8192
#define DK 2048
#define DN 2048

// GEMM tiling: CTA 128x256, 16 warps in 4(M) x 4(N), warp tile 32x64
constexpr int TM = 128;
constexpr int TN = 256;
constexpr int TKC = 64;            // K bytes per pipeline stage
constexpr int ST = 4;              // pipeline stages
constexpr int NK = DK / TKC;       // 32 chunks
constexpr int NT = 512;            // threads per CTA

constexpr int ROWB = 80;           // 64 data + 16 pad -> conflict-free ldmatrix
constexpr int A_ST = TM * ROWB;    // 10240
constexpr int B_ST = TN * ROWB;    // 20480
constexpr int STAGE = A_ST + B_ST; // 30720
constexpr int SMEM_BYTES = ST * STAGE; // 122880

// s8 scratch (allocation-free __device__ globals)
__device__ int8_t g_A[(size_t)DM * DK];
__device__ int8_t g_B[(size_t)DN * DK];

// ---------------- helpers ----------------
__device__ __forceinline__ uint32_t smem_u32(const void* p) {
    uint32_t a;
    asm("{ .reg .u64 t; cvta.to.shared.u64 t, %1; cvt.u32.u64 %0, t; }" : "=r"(a) : "l"(p));
    return a;
}

__device__ __forceinline__ void ldm_x4(uint32_t* r, uint32_t addr) {
    asm volatile("ldmatrix.sync.aligned.m8n8.x4.shared.b16 {%0,%1,%2,%3}, [%4];"
                 : "=r"(r[0]), "=r"(r[1]), "=r"(r[2]), "=r"(r[3]) : "r"(addr));
}

#define CP_ASYNC16(dst_u32, src_ptr) \
    asm volatile("cp.async.cg.shared.global [%0], [%1], 16;" \
                 :: "r"((uint32_t)(dst_u32)), "l"(src_ptr) : "memory")
#define CP_COMMIT() asm volatile("cp.async.commit_group;" ::: "memory")
#define CP_WAIT2()  asm volatile("cp.async.wait_group 2;" ::: "memory")
#define CP_WAIT0()  asm volatile("cp.async.wait_group 0;" ::: "memory")

// s8 MMA: D(16x8,s32) += A(16x32,s8 row) * B(32x8,s8 col)
#define MMA_S8(C, A, B) \
    asm volatile("mma.sync.aligned.m16n8k32.row.col.s32.s8.s8.s32 " \
        "{%0,%1,%2,%3}, {%4,%5,%6,%7}, {%8,%9}, {%0,%1,%2,%3};" \
        : "+r"((C)[0]), "+r"((C)[1]), "+r"((C)[2]), "+r"((C)[3]) \
        : "r"((A)[0]), "r"((A)[1]), "r"((A)[2]), "r"((A)[3]), \
          "r"((B)[0]), "r"((B)[1]))

__device__ __forceinline__ float isgn(int v) {
    return (v > 0) ? 1.0f : ((v < 0) ? -1.0f : 0.0f);
}

// ---------------- conversion: fp32 (+-1) -> s8 (+-1), both tensors in one launch ----
constexpr int NA4 = DM * DK / 4;
constexpr int NW4 = DN * DK / 4;
__global__ void cvt_kernel(const float4* __restrict__ a, const float4* __restrict__ w) {
    int i = blockIdx.x * blockDim.x + threadIdx.x;
    const float4* src;
    uint32_t* dst;
    int idx;
    if (i < NA4) {
        src = a; dst = reinterpret_cast<uint32_t*>(g_A); idx = i;
    } else {
        idx = i - NA4;
        if (idx >= NW4) return;
        src = w; dst = reinterpret_cast<uint32_t*>(g_B);
    }
    float4 v = src[idx];
    uint32_t p = (uint32_t)(uint8_t)(int8_t)(v.x > 0.0f ? 1 : -1)
               | ((uint32_t)(uint8_t)(int8_t)(v.y > 0.0f ? 1 : -1) << 8)
               | ((uint32_t)(uint8_t)(int8_t)(v.z > 0.0f ? 1 : -1) << 16)
               | ((uint32_t)(uint8_t)(int8_t)(v.w > 0.0f ? 1 : -1) << 24);
    dst[idx] = p;
}

// ---------------- GEMM + sign kernel ----------------
// 512 threads = 16 warps, warp grid 4(M) x 4(N), warp tile 32x64.
__global__ void __launch_bounds__(NT, 1) binlinear_gemm_kernel(float* __restrict__ out) {
    extern __shared__ int8_t smem[];
    const uint32_t sb = smem_u32(smem);
    const int tid = threadIdx.x;
    const int wid = tid >> 5;
    const int lane = tid & 31;
    const int g = lane >> 2;      // 0..7
    const int tig = lane & 3;     // 0..3
    const int m0 = blockIdx.y * TM;
    const int n0 = blockIdx.x * TN;
    const int wm = (wid & 3) * 32;      // warp M offset
    const int wn = (wid >> 2) * 64;     // warp N offset

    // ldmatrix per-lane address offsets (verified conflict-free with ROWB=80)
    const uint32_t aoff = (uint32_t)(wm + (lane & 15)) * ROWB + ((lane >> 4) << 4);
    const uint32_t boff = (uint32_t)(wn + (lane >> 4) * 8 + (lane & 7)) * ROWB
                        + ((lane & 8) << 1);

    int c[2][8][4];
    #pragma unroll
    for (int mt = 0; mt < 2; ++mt)
        #pragma unroll
        for (int nt = 0; nt < 8; ++nt)
            #pragma unroll
            for (int r = 0; r < 4; ++r) c[mt][nt][r] = 0;

    const int8_t* gAbase = g_A + (size_t)m0 * DK;
    const int8_t* gBbase = g_B + (size_t)n0 * DK;

    // per stage: A = 512 16B-chunks (1/thread), B = 1024 (2/thread)
    auto load_stage = [&](int s, int kc) {
        const uint32_t Ab = sb + s * STAGE;
        const uint32_t Bb = Ab + A_ST;
        const int8_t* gA = gAbase + kc * TKC;
        const int8_t* gB = gBbase + kc * TKC;
        {
            int row = tid >> 2, seg = tid & 3;
            CP_ASYNC16(Ab + row * ROWB + seg * 16, gA + (size_t)row * DK + seg * 16);
        }
        #pragma unroll
        for (int h = 0; h < 2; ++h) {
            int ch = tid + h * NT;
            int row = ch >> 2, seg = ch & 3;
            CP_ASYNC16(Bb + row * ROWB + seg * 16, gB + (size_t)row * DK + seg * 16);
        }
        CP_COMMIT();
    };

    // prologue: fill ST-1 stages
    #pragma unroll
    for (int s = 0; s < ST - 1; ++s) load_stage(s, s);

    for (int i = 0; i < NK; ++i) {
        if (i < NK - (ST - 1)) CP_WAIT2();
        else                   CP_WAIT0();
        __syncthreads();

        if (i + ST - 1 < NK) load_stage((i + ST - 1) % ST, i + ST - 1);

        const uint32_t Ab = sb + (i % ST) * STAGE;
        const uint32_t Bb = Ab + A_ST;
        #pragma unroll
        for (int ks = 0; ks < 2; ++ks) {
            const int k0 = ks * 32;
            uint32_t a[2][4];
            ldm_x4(a[0], Ab + aoff + k0);
            ldm_x4(a[1], Ab + aoff + 16 * ROWB + k0);
            uint32_t b[8][2];
            #pragma unroll
            for (int p = 0; p < 4; ++p) {
                uint32_t t[4];
                ldm_x4(t, Bb + boff + p * 16 * ROWB + k0);
                b[2 * p + 0][0] = t[0];
                b[2 * p + 0][1] = t[1];
                b[2 * p + 1][0] = t[2];
                b[2 * p + 1][1] = t[3];
            }
            #pragma unroll
            for (int mt = 0; mt < 2; ++mt)
                #pragma unroll
                for (int nt = 0; nt < 8; ++nt)
                    MMA_S8(c[mt][nt], a[mt], b[nt]);
        }
    }

    // ---- epilogue: sign -> float, 8B vectorized stores ----
    #pragma unroll
    for (int mt = 0; mt < 2; ++mt) {
        const int row0 = m0 + wm + mt * 16 + g;
        float* o0 = out + (size_t)row0 * DN + n0 + wn;
        float* o1 = out + (size_t)(row0 + 8) * DN + n0 + wn;
        #pragma unroll
        for (int nt = 0; nt < 8; ++nt) {
            const int col = nt * 8 + tig * 2;
            float2 v0 = make_float2(isgn(c[mt][nt][0]), isgn(c[mt][nt][1]));
            float2 v1 = make_float2(isgn(c[mt][nt][2]), isgn(c[mt][nt][3]));
            *reinterpret_cast<float2*>(o0 + col) = v0;
            *reinterpret_cast<float2*>(o1 + col) = v1;
        }
    }
}

// ---------------- launch ----------------
extern "C" void kernel_launch(void* const* d_in, const int* in_sizes, int n_in,
                              void* d_out, int out_size) {
    const float* a = (const float*)d_in[0];
    const float* w = (const float*)d_in[1];
    if (n_in >= 2 && in_sizes[0] < in_sizes[1]) {
        const float* t = a; a = w; w = t;
    }

    {
        int total = NA4 + NW4;
        cvt_kernel<<<(total + 255) / 256, 256>>>((const float4*)a, (const float4*)w);
    }

    static bool attr_set = false;
    if (!attr_set) {
        cudaFuncSetAttribute(binlinear_gemm_kernel,
                             cudaFuncAttributeMaxDynamicSharedMemorySize, SMEM_BYTES);
        attr_set = true;
    }
    dim3 grid(DN / TN, DM / TM);   // (8, 64)
    binlinear_gemm_kernel<<<grid, NT, SMEM_BYTES>>>((float*)d_out);
}

// round 7
// speedup vs baseline: 1.3304x; 1.3304x over previous
#include <cuda_runtime.h>
#include <cstdint>

// Problem dims
#define DM 8192
#define DK 2048
#define DN 2048

// GEMM tiling: CTA 128x128, 8 warps in 4(M) x 2(N), warp tile 32x64. 2 CTAs/SM.
constexpr int TM = 128;
constexpr int TN = 128;
constexpr int TKC = 128;           // K bytes per pipeline stage (4 ks sub-chunks)
constexpr int ST = 3;              // pipeline stages
constexpr int NK = DK / TKC;       // 16 chunks

constexpr int ROWB = 144;          // 128 data + 16 pad -> conflict-free ldmatrix (4-bank row step)
constexpr int A_ST = TM * ROWB;    // 18432
constexpr int B_ST = TN * ROWB;    // 18432
constexpr int STAGE = A_ST + B_ST; // 36864
constexpr int SMEM_BYTES = ST * STAGE; // 110592 -> 2 CTAs/SM (221184 <= ~227KB)

// s8 scratch (allocation-free __device__ globals)
__device__ int8_t g_A[(size_t)DM * DK];
__device__ int8_t g_B[(size_t)DN * DK];

// ---------------- helpers ----------------
__device__ __forceinline__ uint32_t smem_u32(const void* p) {
    uint32_t a;
    asm("{ .reg .u64 t; cvta.to.shared.u64 t, %1; cvt.u32.u64 %0, t; }" : "=r"(a) : "l"(p));
    return a;
}

__device__ __forceinline__ void ldm_x4(uint32_t* r, uint32_t addr) {
    asm volatile("ldmatrix.sync.aligned.m8n8.x4.shared.b16 {%0,%1,%2,%3}, [%4];"
                 : "=r"(r[0]), "=r"(r[1]), "=r"(r[2]), "=r"(r[3]) : "r"(addr));
}

#define CP_ASYNC16(dst_u32, src_ptr) \
    asm volatile("cp.async.cg.shared.global [%0], [%1], 16;" \
                 :: "r"((uint32_t)(dst_u32)), "l"(src_ptr) : "memory")
#define CP_COMMIT() asm volatile("cp.async.commit_group;" ::: "memory")
#define CP_WAIT1()  asm volatile("cp.async.wait_group 1;" ::: "memory")
#define CP_WAIT0()  asm volatile("cp.async.wait_group 0;" ::: "memory")

// s8 MMA: D(16x8,s32) += A(16x32,s8 row) * B(32x8,s8 col)
#define MMA_S8(C, A, B0, B1) \
    asm volatile("mma.sync.aligned.m16n8k32.row.col.s32.s8.s8.s32 " \
        "{%0,%1,%2,%3}, {%4,%5,%6,%7}, {%8,%9}, {%0,%1,%2,%3};" \
        : "+r"((C)[0]), "+r"((C)[1]), "+r"((C)[2]), "+r"((C)[3]) \
        : "r"((A)[0]), "r"((A)[1]), "r"((A)[2]), "r"((A)[3]), \
          "r"(B0), "r"(B1))

__device__ __forceinline__ float isgn(int v) {
    return (v > 0) ? 1.0f : ((v < 0) ? -1.0f : 0.0f);
}

// ---------------- conversion: fp32 (+-1) -> s8 (+-1), both tensors in one launch ----
constexpr int NA4 = DM * DK / 4;
constexpr int NW4 = DN * DK / 4;
__global__ void cvt_kernel(const float4* __restrict__ a, const float4* __restrict__ w) {
    int i = blockIdx.x * blockDim.x + threadIdx.x;
    const float4* src;
    uint32_t* dst;
    int idx;
    if (i < NA4) {
        src = a; dst = reinterpret_cast<uint32_t*>(g_A); idx = i;
    } else {
        idx = i - NA4;
        if (idx >= NW4) return;
        src = w; dst = reinterpret_cast<uint32_t*>(g_B);
    }
    float4 v = src[idx];
    uint32_t p = (uint32_t)(uint8_t)(int8_t)(v.x > 0.0f ? 1 : -1)
               | ((uint32_t)(uint8_t)(int8_t)(v.y > 0.0f ? 1 : -1) << 8)
               | ((uint32_t)(uint8_t)(int8_t)(v.z > 0.0f ? 1 : -1) << 16)
               | ((uint32_t)(uint8_t)(int8_t)(v.w > 0.0f ? 1 : -1) << 24);
    dst[idx] = p;
}

// ---------------- GEMM + sign kernel ----------------
__global__ void __launch_bounds__(256, 2) binlinear_gemm_kernel(float* __restrict__ out) {
    extern __shared__ int8_t smem[];
    const uint32_t sb = smem_u32(smem);
    const int tid = threadIdx.x;
    const int wid = tid >> 5;
    const int lane = tid & 31;
    const int g = lane >> 2;      // 0..7
    const int tig = lane & 3;     // 0..3
    const int m0 = blockIdx.y * TM;
    const int n0 = blockIdx.x * TN;
    const int wm = (wid & 3) * 32;     // warp M offset
    const int wn = (wid >> 2) * 64;    // warp N offset

    // ldmatrix per-lane address offsets (same mapping verified in R3; ROWB=144 keeps
    // the 4-bank-per-row step -> all 8 rows of a phase hit distinct banks)
    const uint32_t aoff = (uint32_t)(wm + (lane & 15)) * ROWB + ((lane >> 4) << 4);
    const uint32_t boff = (uint32_t)(wn + (lane >> 4) * 8 + (lane & 7)) * ROWB
                        + ((lane & 8) << 1);

    int c[2][8][4];
    #pragma unroll
    for (int mt = 0; mt < 2; ++mt)
        #pragma unroll
        for (int nt = 0; nt < 8; ++nt)
            #pragma unroll
            for (int r = 0; r < 4; ++r) c[mt][nt][r] = 0;

    const int8_t* gAbase = g_A + (size_t)m0 * DK;
    const int8_t* gBbase = g_B + (size_t)n0 * DK;

    // per stage: A = 128 rows x 8 segs = 1024 16B-chunks (4/thread), B same
    auto load_stage = [&](int s, int kc) {
        const uint32_t Ab = sb + s * STAGE;
        const uint32_t Bb = Ab + A_ST;
        const int8_t* gA = gAbase + kc * TKC;
        const int8_t* gB = gBbase + kc * TKC;
        #pragma unroll
        for (int h = 0; h < 4; ++h) {
            int ch = tid + h * 256;
            int row = ch >> 3, seg = ch & 7;
            CP_ASYNC16(Ab + row * ROWB + seg * 16, gA + (size_t)row * DK + seg * 16);
        }
        #pragma unroll
        for (int h = 0; h < 4; ++h) {
            int ch = tid + h * 256;
            int row = ch >> 3, seg = ch & 7;
            CP_ASYNC16(Bb + row * ROWB + seg * 16, gB + (size_t)row * DK + seg * 16);
        }
        CP_COMMIT();
    };

    // prologue: fill ST-1 stages
    #pragma unroll
    for (int s = 0; s < ST - 1; ++s) load_stage(s, s);

    for (int i = 0; i < NK; ++i) {
        if (i < NK - (ST - 1)) CP_WAIT1();
        else                   CP_WAIT0();
        __syncthreads();

        if (i + ST - 1 < NK) load_stage((i + ST - 1) % ST, i + ST - 1);

        const uint32_t Ab = sb + (i % ST) * STAGE;
        const uint32_t Bb = Ab + A_ST;
        #pragma unroll
        for (int ks = 0; ks < 4; ++ks) {
            const int k0 = ks * 32;
            uint32_t a[2][4];
            ldm_x4(a[0], Ab + aoff + k0);
            ldm_x4(a[1], Ab + aoff + 16 * ROWB + k0);
            #pragma unroll
            for (int p = 0; p < 4; ++p) {
                uint32_t t[4];
                ldm_x4(t, Bb + boff + p * 16 * ROWB + k0);
                MMA_S8(c[0][2 * p + 0], a[0], t[0], t[1]);
                MMA_S8(c[0][2 * p + 1], a[0], t[2], t[3]);
                MMA_S8(c[1][2 * p + 0], a[1], t[0], t[1]);
                MMA_S8(c[1][2 * p + 1], a[1], t[2], t[3]);
            }
        }
    }

    // ---- epilogue: sign -> float, 8B vectorized stores ----
    #pragma unroll
    for (int mt = 0; mt < 2; ++mt) {
        const int row0 = m0 + wm + mt * 16 + g;
        float* o0 = out + (size_t)row0 * DN + n0 + wn;
        float* o1 = out + (size_t)(row0 + 8) * DN + n0 + wn;
        #pragma unroll
        for (int nt = 0; nt < 8; ++nt) {
            const int col = nt * 8 + tig * 2;
            float2 v0 = make_float2(isgn(c[mt][nt][0]), isgn(c[mt][nt][1]));
            float2 v1 = make_float2(isgn(c[mt][nt][2]), isgn(c[mt][nt][3]));
            *reinterpret_cast<float2*>(o0 + col) = v0;
            *reinterpret_cast<float2*>(o1 + col) = v1;
        }
    }
}

// ---------------- launch ----------------
extern "C" void kernel_launch(void* const* d_in, const int* in_sizes, int n_in,
                              void* d_out, int out_size) {
    const float* a = (const float*)d_in[0];
    const float* w = (const float*)d_in[1];
    if (n_in >= 2 && in_sizes[0] < in_sizes[1]) {
        const float* t = a; a = w; w = t;
    }

    {
        int total = NA4 + NW4;
        cvt_kernel<<<(total + 255) / 256, 256>>>((const float4*)a, (const float4*)w);
    }

    static bool attr_set = false;
    if (!attr_set) {
        cudaFuncSetAttribute(binlinear_gemm_kernel,
                             cudaFuncAttributeMaxDynamicSharedMemorySize, SMEM_BYTES);
        attr_set = true;
    }
    dim3 grid(DN / TN, DM / TM);   // (16, 64)
    binlinear_gemm_kernel<<<grid, 256, SMEM_BYTES>>>((float*)d_out);
}